// round 16
// baseline (speedup 1.0000x reference)
#include <cuda_runtime.h>
#include <cuda_fp16.h>
#include <cstdint>

// BlockSparse: out = x @ (mask*W)^T + bias.  M=8192, N=4096, K=4096 fp32.
// Mask: 256-blocks, keep (i,j) iff (i+j)%16 >= 8 -> K_eff = 2048 per column block.
//
// R16: R15 structure (fp16 m16n8k16, warp 64x64, CTA 128x128, 3-stage
// cp.async, 2 CTAs/SM, persistent 304 CTAs, interleaved issue) plus
// CONVERSION OVERLAP: prepass converts only w + x m-blocks 0..9 (~13us);
// x blocks 10..63 are converted inside the tensor-bound GEMM (during gen j,
// CTAs cooperatively convert blocks 10+10j..19+10j), with per-block arrival
// counters; consumers spin (rarely) before cross-tile lookahead loads.

#define M_DIM 8192
#define N_DIM 4096
#define K_DIM 4096

#define BM 128
#define BN 128
#define BK 64
#define NTILES 2048
#define GRID_P 304
#define STAGES 3
#define A_PART (128 * 128)
#define B_PART (128 * 128)
#define OFF_A 0
#define OFF_B (A_PART)
#define STAGE_BYTES (A_PART + B_PART)      // 32 KB
#define SMEM_DYN (STAGES * STAGE_BYTES + 256)

__device__ __half g_x[(size_t)M_DIM * K_DIM];
__device__ __half g_w[(size_t)N_DIM * K_DIM];
__device__ int    g_cnt[64];               // x m-block ready counters (target 32)

// ---------- helpers ----------
__device__ __forceinline__ uint32_t smem_u32(const void* p) {
    uint32_t a;
    asm("{ .reg .u64 t; cvta.to.shared.u64 t, %1; cvt.u32.u64 %0, t; }" : "=r"(a) : "l"(p));
    return a;
}
__device__ __forceinline__ void cp16(uint32_t dst, const void* src) {
    asm volatile("cp.async.cg.shared.global [%0], [%1], 16;" :: "r"(dst), "l"(src));
}
__device__ __forceinline__ void cp_commit() { asm volatile("cp.async.commit_group;" ::: "memory"); }
template <int N> __device__ __forceinline__ void cp_wait() {
    asm volatile("cp.async.wait_group %0;" :: "n"(N) : "memory");
}
__device__ __forceinline__ void ldsm_x4(uint32_t* r, uint32_t addr) {
    asm volatile("ldmatrix.sync.aligned.m8n8.x4.shared.b16 {%0,%1,%2,%3}, [%4];"
                 : "=r"(r[0]), "=r"(r[1]), "=r"(r[2]), "=r"(r[3]) : "r"(addr));
}
__device__ __forceinline__ void mma_f16(float* c, const uint32_t* a, const uint32_t* b) {
    asm volatile(
        "mma.sync.aligned.m16n8k16.row.col.f32.f16.f16.f32 "
        "{%0,%1,%2,%3}, {%4,%5,%6,%7}, {%8,%9}, {%0,%1,%2,%3};"
        : "+f"(c[0]), "+f"(c[1]), "+f"(c[2]), "+f"(c[3])
        : "r"(a[0]), "r"(a[1]), "r"(a[2]), "r"(a[3]), "r"(b[0]), "r"(b[1]));
}
__device__ __forceinline__ uint32_t swz(int r, int c) {
    return (uint32_t)(r * 128 + ((c ^ (r & 7)) << 4));
}
__device__ __forceinline__ uint4 cvt8(float4 v0, float4 v1) {
    __half2 h0 = __floats2half2_rn(v0.x, v0.y);
    __half2 h1 = __floats2half2_rn(v0.z, v0.w);
    __half2 h2 = __floats2half2_rn(v1.x, v1.y);
    __half2 h3 = __floats2half2_rn(v1.z, v1.w);
    uint4 pk;
    pk.x = *reinterpret_cast<uint32_t*>(&h0);
    pk.y = *reinterpret_cast<uint32_t*>(&h1);
    pk.z = *reinterpret_cast<uint32_t*>(&h2);
    pk.w = *reinterpret_cast<uint32_t*>(&h3);
    return pk;
}

// ---------- prepass: w (kept blocks) + x m-blocks 0..9; zero counters ----------
__global__ __launch_bounds__(256) void cvt_kernel(const float* __restrict__ x,
                                                  const float* __restrict__ w) {
    if (blockIdx.x == 0 && threadIdx.x < 64) g_cnt[threadIdx.x] = 0;

    const long NX8 = 1280L * (K_DIM / 8);         // x m-blocks 0..9
    const long NW8 = (long)N_DIM * 8 * 32;        // kept w groups
    const long NT = NX8 + NW8;
    long stride = (long)gridDim.x * blockDim.x;
    for (long t = (long)blockIdx.x * blockDim.x + threadIdx.x; t < NT; t += stride) {
        long o8;
        const float* src;
        __half* dst;
        if (t < NX8) {
            o8 = t;
            src = x;
            dst = g_x;
        } else {
            const long u = t - NX8;
            const int row = (int)(u >> 8);
            const int rem = (int)(u & 255);
            const int kb = rem >> 5;
            const int f8 = rem & 31;
            const int i = row >> 8;
            const int j = (8 + kb - (i & 15)) & 15;
            o8 = (long)row * (K_DIM / 8) + j * 32 + f8;
            src = w;
            dst = g_w;
        }
        float4 v0 = reinterpret_cast<const float4*>(src)[2 * o8];
        float4 v1 = reinterpret_cast<const float4*>(src)[2 * o8 + 1];
        reinterpret_cast<uint4*>(dst)[o8] = cvt8(v0, v1);
    }
}

// ---------- main GEMM (persistent, overlapped x conversion) ----------
__global__ __launch_bounds__(128, 2)
void bs_f16_kernel(const float* __restrict__ xin,
                   const float* __restrict__ bias, float* __restrict__ out) {
    extern __shared__ char smem[];
    const uint32_t sbase = smem_u32(smem);

    const int tid = threadIdx.x;
    const int wid = tid >> 5;
    const int lane = tid & 31;
    const int wm = wid & 1;
    const int wn = wid >> 1;
    const int t0 = blockIdx.x;

    int nT = 0;
    for (int t = t0; t < NTILES; t += GRID_P) nT++;
    const int gcEnd = nT * 32;
    if (gcEnd == 0) return;

    auto tileMB = [&](int j) { return ((t0 + GRID_P * j) >> 5) * BM; };
    auto tileNB = [&](int j) { return ((t0 + GRID_P * j) & 31) * BN; };
    auto chunkK0 = [&](int i, int cc) {
        const int kb = cc >> 2;
        const int j = (8 + kb - (i & 15)) & 15;
        return j * 256 + (cc & 3) * BK;
    };

    auto cp_piece = [&](int lmB, int lnB, int lk0, uint32_t st, int ii) {
        const int idx = tid + ii * 128;
        uint32_t dst;
        const __half* src;
        if (idx < 1024) {
            const int r = idx >> 3, cc = idx & 7;
            src = g_x + ((size_t)(lmB + r) * K_DIM + lk0 + cc * 8);
            dst = st + OFF_A + swz(r, cc);
        } else {
            const int t = idx - 1024;
            const int r = t >> 3, cc = t & 7;
            src = g_w + ((size_t)(lnB + r) * K_DIM + lk0 + cc * 8);
            dst = st + OFF_B + swz(r, cc);
        }
        cp16(dst, src);
    };

    // convert one 4-row slice s of x m-block b (128 threads, 16 groups each)
    auto convert_slice = [&](int b, int s) {
        const long base = ((long)b * 128 + (long)s * 4) * (K_DIM / 8) + (long)tid * 16;
        const float4* xs = reinterpret_cast<const float4*>(xin);
        uint4* xd = reinterpret_cast<uint4*>(g_x);
#pragma unroll
        for (int g = 0; g < 16; g++) {
            const long o8 = base + g;
            xd[o8] = cvt8(xs[2 * o8], xs[2 * o8 + 1]);
        }
    };

    const int q = lane >> 3;
    const int l7 = lane & 7;
    const int qa = q >> 1;
    const int qb = q & 1;
    const uint32_t aOff0 = OFF_A + (uint32_t)(wm * 64 + ((q & 1) << 3) + l7) * 128;
    const uint32_t bOff0 = OFF_B + (uint32_t)(wn * 64 + ((q >> 1) << 3) + l7) * 128;

    float acc[4][8][4];
#pragma unroll
    for (int a = 0; a < 4; a++)
#pragma unroll
        for (int b = 0; b < 8; b++)
#pragma unroll
            for (int p = 0; p < 4; p++) acc[a][b][p] = 0.0f;

    uint32_t af[2][4][4];
    uint32_t bf[2][16];

    // prologue: chunks 0 and 1 of tile 0 (m-block <= 9, preconverted)
    {
        const int mB = tileMB(0), nB = tileNB(0), i = (tileNB(0) / BN) >> 1;
#pragma unroll
        for (int ii = 0; ii < 16; ii++) cp_piece(mB, nB, chunkK0(i, 0), sbase, ii);
        cp_commit();
        const uint32_t s1 = sbase + STAGE_BYTES;
#pragma unroll
        for (int ii = 0; ii < 16; ii++) cp_piece(mB, nB, chunkK0(i, 1), s1, ii);
        cp_commit();
        cp_wait<1>();
        __syncthreads();
        const uint32_t tA = (uint32_t)((qa ^ l7) << 4);
        const uint32_t tB = (uint32_t)((qb ^ l7) << 4);
#pragma unroll
        for (int mi = 0; mi < 4; mi++)
            ldsm_x4(af[0][mi], sbase + aOff0 + (uint32_t)(mi * 2048) + tA);
#pragma unroll
        for (int nip = 0; nip < 4; nip++)
            ldsm_x4(&bf[0][nip * 4], sbase + bOff0 + (uint32_t)(nip * 2048) + tB);
    }

    int cmB = tileMB(0), cnB = tileNB(0);

#pragma unroll 1
    for (int gc = 0; gc < gcEnd; gc++) {
        const int cc = gc & 31;
        const uint32_t st  = sbase + (uint32_t)(gc % STAGES) * STAGE_BYTES;
        const uint32_t stn = sbase + (uint32_t)((gc + 1) % STAGES) * STAGE_BYTES;

        const bool doLoad = (gc + 2 < gcEnd);
        int lmB = 0, lnB = 0, lk0 = 0;
        uint32_t lst = 0;
        if (doLoad) {
            const int lj = (gc + 2) >> 5;
            lmB = tileMB(lj);
            lnB = tileNB(lj);
            lk0 = chunkK0((lnB / BN) >> 1, (gc + 2) & 31);
            lst = sbase + (uint32_t)((gc + 2) % STAGES) * STAGE_BYTES;
        }

        // consumer spin: next tile's m-block must be converted before its loads
        if (cc == 30 && doLoad) {
            const int b = lmB >> 7;
            if (b >= 10) {
                if (tid == 0) {
                    while (*(volatile int*)&g_cnt[b] < 32) { }
                    __threadfence();
                }
                __syncthreads();
            }
        }

#pragma unroll
        for (int kstep = 0; kstep < 4; kstep++) {
            const int cur = kstep & 1, nxt = cur ^ 1;

            uint32_t ldb;
            int lkk;
            bool doFrag;
            if (kstep < 3) {
                ldb = st; lkk = kstep + 1; doFrag = true;
            } else {
                cp_wait<1>();
                __syncthreads();
                ldb = stn; lkk = 0; doFrag = (gc + 1 < gcEnd);
            }
            const uint32_t aBase = ldb + aOff0 + (uint32_t)(((2 * lkk + qa) ^ l7) << 4);
            const uint32_t bBase = ldb + bOff0 + (uint32_t)(((2 * lkk + qb) ^ l7) << 4);
            const bool doCp = doLoad && (kstep < 2);

#pragma unroll
            for (int nip = 0; nip < 4; nip++) {
                if (doFrag) ldsm_x4(af[nxt][nip], aBase + (uint32_t)(nip * 2048));
#pragma unroll
                for (int mi = 0; mi < 4; mi++)
                    mma_f16(acc[mi][2 * nip], af[cur][mi], &bf[cur][nip * 4]);
                if (doFrag) ldsm_x4(&bf[nxt][nip * 4], bBase + (uint32_t)(nip * 2048));
#pragma unroll
                for (int mi = 0; mi < 4; mi++)
                    mma_f16(acc[mi][2 * nip + 1], af[cur][mi], &bf[cur][nip * 4 + 2]);
                if (doCp) {
                    cp_piece(lmB, lnB, lk0, lst, kstep * 8 + nip * 2);
                    cp_piece(lmB, lnB, lk0, lst, kstep * 8 + nip * 2 + 1);
                }
            }
            if (doCp && kstep == 1) cp_commit();
        }

        // injected x conversion for generation j+1's blocks (early in tile)
        {
            const int j = gc >> 5;
            if (cc == 2 && j <= 5) {
                const int b1 = 10 + 10 * j + (t0 >> 5);
                const int b2 = (t0 < 16) ? (19 + 10 * j) : -1;
                if (b1 <= 63) convert_slice(b1, t0 & 31);
                if (b2 >= 0 && b2 <= 63) convert_slice(b2, t0 + 16);
                __threadfence();
                __syncthreads();
                if (tid == 0) {
                    if (b1 <= 63) atomicAdd(&g_cnt[b1], 1);
                    if (b2 >= 0 && b2 <= 63) atomicAdd(&g_cnt[b2], 1);
                }
            }
        }

        // tile finished: epilogue
        if (cc == 31) {
            const int qid = lane >> 2;
            const int qn = (lane & 3) * 2;
#pragma unroll
            for (int mi = 0; mi < 4; mi++) {
                const int m0 = cmB + wm * 64 + mi * 16 + qid;
#pragma unroll
                for (int ni = 0; ni < 8; ni++) {
                    const int ncol = wn * 64 + ni * 8 + qn;
                    const float2 bv = __ldg(reinterpret_cast<const float2*>(&bias[cnB + ncol]));
                    float2 o0 = make_float2(acc[mi][ni][0] + bv.x, acc[mi][ni][1] + bv.y);
                    float2 o1 = make_float2(acc[mi][ni][2] + bv.x, acc[mi][ni][3] + bv.y);
                    *reinterpret_cast<float2*>(&out[(size_t)m0 * N_DIM + cnB + ncol]) = o0;
                    *reinterpret_cast<float2*>(&out[(size_t)(m0 + 8) * N_DIM + cnB + ncol]) = o1;
                    acc[mi][ni][0] = 0.0f; acc[mi][ni][1] = 0.0f;
                    acc[mi][ni][2] = 0.0f; acc[mi][ni][3] = 0.0f;
                }
            }
            if (gc + 1 < gcEnd) {
                const int nj = (gc + 1) >> 5;
                cmB = tileMB(nj);
                cnB = tileNB(nj);
            }
        }
    }
}

// ---------- launch ----------
extern "C" void kernel_launch(void* const* d_in, const int* in_sizes, int n_in,
                              void* d_out, int out_size) {
    const float* x    = (const float*)d_in[0];
    const float* w    = (const float*)d_in[1];
    const float* bias = (const float*)d_in[2];
    float* out = (float*)d_out;

    cvt_kernel<<<6144, 256>>>(x, w);

    cudaFuncSetAttribute(bs_f16_kernel, cudaFuncAttributeMaxDynamicSharedMemorySize, SMEM_DYN);
    bs_f16_kernel<<<GRID_P, 128, SMEM_DYN>>>(x, bias, out);
}

// round 17
// speedup vs baseline: 1.2235x; 1.2235x over previous
#include <cuda_runtime.h>
#include <cuda_fp16.h>
#include <cstdint>

// BlockSparse: out = x @ (mask*W)^T + bias.  M=8192, N=4096, K=4096 fp32.
// Mask: 256-blocks, keep (i,j) iff (i+j)%16 >= 8 -> K_eff = 2048 per column block.
//
// R17: revert to R15 (best GEMM: fp16 m16n8k16, warp 64x64, CTA 128x128,
// 3-stage cp.async, 2 CTAs/SM, persistent 304 CTAs, interleaved issue).
// Prepass tuned: fp32 source reads use ld.global.cs (evict-first, data is
// dead after conversion) so the fp16 outputs (96MB, L2-resident) survive;
// larger grid for DRAM MLP.

#define M_DIM 8192
#define N_DIM 4096
#define K_DIM 4096

#define BM 128
#define BN 128
#define BK 64
#define NTILES 2048
#define GRID_P 304
#define STAGES 3
#define A_PART (128 * 128)
#define B_PART (128 * 128)
#define OFF_A 0
#define OFF_B (A_PART)
#define STAGE_BYTES (A_PART + B_PART)      // 32 KB
#define SMEM_DYN (STAGES * STAGE_BYTES + 256)

__device__ __half g_x[(size_t)M_DIM * K_DIM];
__device__ __half g_w[(size_t)N_DIM * K_DIM];

// ---------- helpers ----------
__device__ __forceinline__ uint32_t smem_u32(const void* p) {
    uint32_t a;
    asm("{ .reg .u64 t; cvta.to.shared.u64 t, %1; cvt.u32.u64 %0, t; }" : "=r"(a) : "l"(p));
    return a;
}
__device__ __forceinline__ void cp16(uint32_t dst, const void* src) {
    asm volatile("cp.async.cg.shared.global [%0], [%1], 16;" :: "r"(dst), "l"(src));
}
__device__ __forceinline__ void cp_commit() { asm volatile("cp.async.commit_group;" ::: "memory"); }
template <int N> __device__ __forceinline__ void cp_wait() {
    asm volatile("cp.async.wait_group %0;" :: "n"(N) : "memory");
}
__device__ __forceinline__ void ldsm_x4(uint32_t* r, uint32_t addr) {
    asm volatile("ldmatrix.sync.aligned.m8n8.x4.shared.b16 {%0,%1,%2,%3}, [%4];"
                 : "=r"(r[0]), "=r"(r[1]), "=r"(r[2]), "=r"(r[3]) : "r"(addr));
}
__device__ __forceinline__ void mma_f16(float* c, const uint32_t* a, const uint32_t* b) {
    asm volatile(
        "mma.sync.aligned.m16n8k16.row.col.f32.f16.f16.f32 "
        "{%0,%1,%2,%3}, {%4,%5,%6,%7}, {%8,%9}, {%0,%1,%2,%3};"
        : "+f"(c[0]), "+f"(c[1]), "+f"(c[2]), "+f"(c[3])
        : "r"(a[0]), "r"(a[1]), "r"(a[2]), "r"(a[3]), "r"(b[0]), "r"(b[1]));
}
__device__ __forceinline__ uint32_t swz(int r, int c) {
    return (uint32_t)(r * 128 + ((c ^ (r & 7)) << 4));
}
__device__ __forceinline__ float4 ldcs4(const float4* p) {
    float4 v;
    asm volatile("ld.global.cs.v4.f32 {%0,%1,%2,%3}, [%4];"
                 : "=f"(v.x), "=f"(v.y), "=f"(v.z), "=f"(v.w) : "l"(p));
    return v;
}

// ---------- prepass: fp32 -> fp16 (evict-first reads, 16B stores) ----------
__global__ __launch_bounds__(256) void cvt_kernel(const float* __restrict__ x,
                                                  const float* __restrict__ w) {
    const long NX8 = (long)M_DIM * K_DIM / 8;
    const long NW8 = (long)N_DIM * 8 * 32;        // kept-w groups only
    const long NT = NX8 + NW8;
    long stride = (long)gridDim.x * blockDim.x;
    for (long t = (long)blockIdx.x * blockDim.x + threadIdx.x; t < NT; t += stride) {
        long o8;
        const float* src;
        __half* dst;
        if (t < NX8) {
            o8 = t;
            src = x;
            dst = g_x;
        } else {
            const long u = t - NX8;
            const int row = (int)(u >> 8);
            const int rem = (int)(u & 255);
            const int kb = rem >> 5;
            const int f8 = rem & 31;
            const int i = row >> 8;
            const int j = (8 + kb - (i & 15)) & 15;
            o8 = (long)row * (K_DIM / 8) + j * 32 + f8;
            src = w;
            dst = g_w;
        }
        float4 v0 = ldcs4(reinterpret_cast<const float4*>(src) + 2 * o8);
        float4 v1 = ldcs4(reinterpret_cast<const float4*>(src) + 2 * o8 + 1);
        __half2 h0 = __floats2half2_rn(v0.x, v0.y);
        __half2 h1 = __floats2half2_rn(v0.z, v0.w);
        __half2 h2 = __floats2half2_rn(v1.x, v1.y);
        __half2 h3 = __floats2half2_rn(v1.z, v1.w);
        uint4 pk;
        pk.x = *reinterpret_cast<uint32_t*>(&h0);
        pk.y = *reinterpret_cast<uint32_t*>(&h1);
        pk.z = *reinterpret_cast<uint32_t*>(&h2);
        pk.w = *reinterpret_cast<uint32_t*>(&h3);
        reinterpret_cast<uint4*>(dst)[o8] = pk;
    }
}

// ---------- main GEMM (persistent, interleaved issue) ----------
__global__ __launch_bounds__(128, 2)
void bs_f16_kernel(const float* __restrict__ bias, float* __restrict__ out) {
    extern __shared__ char smem[];
    const uint32_t sbase = smem_u32(smem);

    const int tid = threadIdx.x;
    const int wid = tid >> 5;
    const int lane = tid & 31;
    const int wm = wid & 1;
    const int wn = wid >> 1;
    const int t0 = blockIdx.x;

    int nT = 0;
    for (int t = t0; t < NTILES; t += GRID_P) nT++;
    const int gcEnd = nT * 32;
    if (gcEnd == 0) return;

    auto tileMB = [&](int j) { return ((t0 + GRID_P * j) >> 5) * BM; };
    auto tileNB = [&](int j) { return ((t0 + GRID_P * j) & 31) * BN; };
    auto chunkK0 = [&](int i, int cc) {
        const int kb = cc >> 2;
        const int j = (8 + kb - (i & 15)) & 15;
        return j * 256 + (cc & 3) * BK;
    };

    auto cp_piece = [&](int lmB, int lnB, int lk0, uint32_t st, int ii) {
        const int idx = tid + ii * 128;
        uint32_t dst;
        const __half* src;
        if (idx < 1024) {
            const int r = idx >> 3, cc = idx & 7;
            src = g_x + ((size_t)(lmB + r) * K_DIM + lk0 + cc * 8);
            dst = st + OFF_A + swz(r, cc);
        } else {
            const int t = idx - 1024;
            const int r = t >> 3, cc = t & 7;
            src = g_w + ((size_t)(lnB + r) * K_DIM + lk0 + cc * 8);
            dst = st + OFF_B + swz(r, cc);
        }
        cp16(dst, src);
    };

    const int q = lane >> 3;
    const int l7 = lane & 7;
    const int qa = q >> 1;
    const int qb = q & 1;
    const uint32_t aOff0 = OFF_A + (uint32_t)(wm * 64 + ((q & 1) << 3) + l7) * 128;
    const uint32_t bOff0 = OFF_B + (uint32_t)(wn * 64 + ((q >> 1) << 3) + l7) * 128;

    float acc[4][8][4];
#pragma unroll
    for (int a = 0; a < 4; a++)
#pragma unroll
        for (int b = 0; b < 8; b++)
#pragma unroll
            for (int p = 0; p < 4; p++) acc[a][b][p] = 0.0f;

    uint32_t af[2][4][4];
    uint32_t bf[2][16];

    // prologue: chunks 0 and 1 of tile 0; fragments for kstep 0
    {
        const int mB = tileMB(0), nB = tileNB(0), i = (tileNB(0) / BN) >> 1;
#pragma unroll
        for (int ii = 0; ii < 16; ii++) cp_piece(mB, nB, chunkK0(i, 0), sbase, ii);
        cp_commit();
        const uint32_t s1 = sbase + STAGE_BYTES;
#pragma unroll
        for (int ii = 0; ii < 16; ii++) cp_piece(mB, nB, chunkK0(i, 1), s1, ii);
        cp_commit();
        cp_wait<1>();
        __syncthreads();
        const uint32_t tA = (uint32_t)((qa ^ l7) << 4);
        const uint32_t tB = (uint32_t)((qb ^ l7) << 4);
#pragma unroll
        for (int mi = 0; mi < 4; mi++)
            ldsm_x4(af[0][mi], sbase + aOff0 + (uint32_t)(mi * 2048) + tA);
#pragma unroll
        for (int nip = 0; nip < 4; nip++)
            ldsm_x4(&bf[0][nip * 4], sbase + bOff0 + (uint32_t)(nip * 2048) + tB);
    }

    int cmB = tileMB(0), cnB = tileNB(0);

#pragma unroll 1
    for (int gc = 0; gc < gcEnd; gc++) {
        const int cc = gc & 31;
        const uint32_t st  = sbase + (uint32_t)(gc % STAGES) * STAGE_BYTES;
        const uint32_t stn = sbase + (uint32_t)((gc + 1) % STAGES) * STAGE_BYTES;

        const bool doLoad = (gc + 2 < gcEnd);
        int lmB = 0, lnB = 0, lk0 = 0;
        uint32_t lst = 0;
        if (doLoad) {
            const int lj = (gc + 2) >> 5;
            lmB = tileMB(lj);
            lnB = tileNB(lj);
            lk0 = chunkK0((lnB / BN) >> 1, (gc + 2) & 31);
            lst = sbase + (uint32_t)((gc + 2) % STAGES) * STAGE_BYTES;
        }

#pragma unroll
        for (int kstep = 0; kstep < 4; kstep++) {
            const int cur = kstep & 1, nxt = cur ^ 1;

            uint32_t ldb;
            int lkk;
            bool doFrag;
            if (kstep < 3) {
                ldb = st; lkk = kstep + 1; doFrag = true;
            } else {
                cp_wait<1>();
                __syncthreads();
                ldb = stn; lkk = 0; doFrag = (gc + 1 < gcEnd);
            }
            const uint32_t aBase = ldb + aOff0 + (uint32_t)(((2 * lkk + qa) ^ l7) << 4);
            const uint32_t bBase = ldb + bOff0 + (uint32_t)(((2 * lkk + qb) ^ l7) << 4);
            const bool doCp = doLoad && (kstep < 2);

            // interleaved issue: per nip group -> 1 LDSM, 4 MMA, 1 LDSM, 4 MMA, 2 cp
#pragma unroll
            for (int nip = 0; nip < 4; nip++) {
                if (doFrag) ldsm_x4(af[nxt][nip], aBase + (uint32_t)(nip * 2048));
#pragma unroll
                for (int mi = 0; mi < 4; mi++)
                    mma_f16(acc[mi][2 * nip], af[cur][mi], &bf[cur][nip * 4]);
                if (doFrag) ldsm_x4(&bf[nxt][nip * 4], bBase + (uint32_t)(nip * 2048));
#pragma unroll
                for (int mi = 0; mi < 4; mi++)
                    mma_f16(acc[mi][2 * nip + 1], af[cur][mi], &bf[cur][nip * 4 + 2]);
                if (doCp) {
                    cp_piece(lmB, lnB, lk0, lst, kstep * 8 + nip * 2);
                    cp_piece(lmB, lnB, lk0, lst, kstep * 8 + nip * 2 + 1);
                }
            }
            if (doCp && kstep == 1) cp_commit();
        }

        // tile finished: epilogue (overlaps in-flight cp.async for gc+2)
        if (cc == 31) {
            const int qid = lane >> 2;
            const int qn = (lane & 3) * 2;
#pragma unroll
            for (int mi = 0; mi < 4; mi++) {
                const int m0 = cmB + wm * 64 + mi * 16 + qid;
#pragma unroll
                for (int ni = 0; ni < 8; ni++) {
                    const int ncol = wn * 64 + ni * 8 + qn;
                    const float2 bv = __ldg(reinterpret_cast<const float2*>(&bias[cnB + ncol]));
                    float2 o0 = make_float2(acc[mi][ni][0] + bv.x, acc[mi][ni][1] + bv.y);
                    float2 o1 = make_float2(acc[mi][ni][2] + bv.x, acc[mi][ni][3] + bv.y);
                    *reinterpret_cast<float2*>(&out[(size_t)m0 * N_DIM + cnB + ncol]) = o0;
                    *reinterpret_cast<float2*>(&out[(size_t)(m0 + 8) * N_DIM + cnB + ncol]) = o1;
                    acc[mi][ni][0] = 0.0f; acc[mi][ni][1] = 0.0f;
                    acc[mi][ni][2] = 0.0f; acc[mi][ni][3] = 0.0f;
                }
            }
            if (gc + 1 < gcEnd) {
                const int nj = (gc + 1) >> 5;
                cmB = tileMB(nj);
                cnB = tileNB(nj);
            }
        }
    }
}

// ---------- launch ----------
extern "C" void kernel_launch(void* const* d_in, const int* in_sizes, int n_in,
                              void* d_out, int out_size) {
    const float* x    = (const float*)d_in[0];
    const float* w    = (const float*)d_in[1];
    const float* bias = (const float*)d_in[2];
    float* out = (float*)d_out;

    cvt_kernel<<<8192, 256>>>(x, w);

    cudaFuncSetAttribute(bs_f16_kernel, cudaFuncAttributeMaxDynamicSharedMemorySize, SMEM_DYN);
    bs_f16_kernel<<<GRID_P, 128, SMEM_DYN>>>(bias, out);
}